// round 13
// baseline (speedup 1.0000x reference)
#include <cuda_runtime.h>
#include <math.h>

#define NSIG 65536
#define NAT  512
#define MDIM 64
#define NBLK 2048            // NSIG / 32 signals per block
#define SMEM_FLOATS (2048 + 2112)
#define SMEM_BYTES  (SMEM_FLOATS * 4)

// ---------------- device globals (scratch; no allocations allowed) ----------
__device__ __align__(16) float  g_dnormJ[MDIM][NAT];   // [m][j]
__device__ __align__(16) float  g_dnormT[NAT][MDIM];   // [j][m]
__device__ __align__(16) float  g_G[NAT][NAT];         // Gram (scaled)
// h_bar staging: per block 8192 u64 (32 signals x 8 pairs x 32 lanes) = 64KB.
// Written once / read once per block => stays L2-resident; frees smem so the
// L1D carveout grows 64KB -> ~190KB and Gram rows survive between iterations.
__device__ __align__(16) unsigned long long g_hbar[(size_t)NBLK * 8192];
__device__ double g_partial[NBLK];
__device__ unsigned g_done = 0;

// ---------------- f32x2 packed-FMA helpers (Blackwell) ----------------------
__device__ __forceinline__ unsigned long long fma2(unsigned long long a,
                                                   unsigned long long b,
                                                   unsigned long long c) {
    unsigned long long r;
    asm("fma.rn.f32x2 %0, %1, %2, %3;" : "=l"(r) : "l"(a), "l"(b), "l"(c));
    return r;
}
__device__ __forceinline__ unsigned long long pack2(float x) {
    unsigned long long r;
    asm("mov.b64 %0, {%1, %1};" : "=l"(r) : "f"(x));
    return r;
}
__device__ __forceinline__ unsigned long long pk2(float a, float b) {
    unsigned long long r;
    asm("mov.b64 %0, {%1, %2};" : "=l"(r) : "f"(a), "f"(b));
    return r;
}
__device__ __forceinline__ float2 unpack2(unsigned long long v) {
    float2 f;
    asm("mov.b64 {%0, %1}, %2;" : "=f"(f.x), "=f"(f.y) : "l"(v));
    return f;
}

// ---------------- K-prologue: ONE launch computes everything ----------------
__global__ void k_prep1(const float* __restrict__ dict) {
    __shared__ float di[MDIM];
    __shared__ float rni_sh;
    const int i = blockIdx.x, tid = threadIdx.x;
    if (tid < MDIM) di[tid] = __ldg(dict + tid * NAT + i);
    __syncthreads();

    const int j0 = tid, j1 = tid + 256;
    float s0 = 0.f, s1 = 0.f, g0 = 0.f, g1 = 0.f;
    #pragma unroll
    for (int m = 0; m < MDIM; m++) {
        float a  = __ldg(dict + m * NAT + j0);
        float bb = __ldg(dict + m * NAT + j1);
        float dm = di[m];
        s0 += a * a;   s1 += bb * bb;
        g0 += dm * a;  g1 += dm * bb;
    }
    float rn0 = 1.f / fmaxf(sqrtf(s0), 1e-10f);
    float rn1 = 1.f / fmaxf(sqrtf(s1), 1e-10f);
    if (j0 == i) rni_sh = rn0;
    if (j1 == i) rni_sh = rn1;
    __syncthreads();
    const float rni = rni_sh;

    g_G[i][j0] = g0 * rni * rn0;
    g_G[i][j1] = g1 * rni * rn1;

    if (tid < MDIM) {                 // dnorm column i
        float d = di[tid] * rni;
        g_dnormJ[tid][i] = d;
        g_dnormT[i][tid] = d;
    }
}

// atom index owned by (lane, t):  j = 128*(t>>2) + 4*lane + (t&3)
#define JMAP(lane, t) (128 * ((t) >> 2) + 4 * (lane) + ((t) & 3))
#define TRI(i, j) ((i) * ((i) - 1) / 2 + (j))    // lower-tri flat index, i > j

// local masked abs-argmax over 16 owned atoms kept as 8 f32x2 pairs
#define LOCAL_ARGMAX64(h8, mk, LABS, LJ, LSGN) do {                          \
    float v8[8]; int m8[8];                                                  \
    _Pragma("unroll")                                                        \
    for (int p = 0; p < 8; p++) {                                            \
        float2 f = unpack2((h8)[p]);                                         \
        unsigned hb0 = __float_as_uint(f.x);                                 \
        unsigned hb1 = __float_as_uint(f.y);                                 \
        float a0 = (((mk) >> (2*p)) & 1u) ? 0.f                              \
                 : __uint_as_float(hb0 & 0x7FFFFFFFu);                       \
        float a1 = (((mk) >> (2*p+1)) & 1u) ? 0.f                            \
                 : __uint_as_float(hb1 & 0x7FFFFFFFu);                       \
        bool r = a1 > a0;                                                    \
        v8[p] = r ? a1 : a0;                                                 \
        m8[p] = r ? (((2*p+1) << 1) | (int)(hb1 >> 31))                      \
                  : (((2*p)   << 1) | (int)(hb0 >> 31));                     \
    }                                                                        \
    float v4[4]; int m4[4];                                                  \
    _Pragma("unroll")                                                        \
    for (int p = 0; p < 4; p++) {                                            \
        bool r = v8[2*p+1] > v8[2*p];                                        \
        v4[p] = r ? v8[2*p+1] : v8[2*p];                                     \
        m4[p] = r ? m8[2*p+1] : m8[2*p];                                     \
    }                                                                        \
    float v2[2]; int m2[2];                                                  \
    _Pragma("unroll")                                                        \
    for (int p = 0; p < 2; p++) {                                            \
        bool r = v4[2*p+1] > v4[2*p];                                        \
        v2[p] = r ? v4[2*p+1] : v4[2*p];                                     \
        m2[p] = r ? m4[2*p+1] : m4[2*p];                                     \
    }                                                                        \
    bool r1 = v2[1] > v2[0];                                                 \
    float lv = r1 ? v2[1] : v2[0];                                           \
    int   lm = r1 ? m2[1] : m2[0];                                           \
    (LABS) = __float_as_uint(lv);                                            \
    (LJ)   = (unsigned)JMAP(lane, lm >> 1);                                  \
    (LSGN) = (unsigned)(lm & 1);                                             \
} while (0)

// ---------------- K3: fused zero + GEMM + dual-chain OMP + outputs + loss ---
__global__ void __launch_bounds__(256, 2)
k_main(const float* __restrict__ ze, float* __restrict__ out_z,
       float* __restrict__ out_coef, float* __restrict__ out_loss) {
    extern __shared__ float smem[];
    float* sh_x = smem;                                       // [64][32]  2048
    float* sh_z = smem + 2048;                                // [64][33]  2112
    __shared__ double sh_red[256];
    __shared__ int sh_last;

    const int tid  = threadIdx.x;
    const int lane = tid & 31;
    const int wid  = tid >> 5;
    const int tile = blockIdx.x * 32;
    const int b    = tile >> 10;
    const int hw0  = tile & 1023;
    const float* zb = ze + (size_t)b * 65536 + hw0;
    unsigned long long* hb_blk = g_hbar + (size_t)blockIdx.x * 8192;

    // ---- zero this block's 32 coeff columns (hides under GEMM) ----
    {
        float* cz = out_coef + tile;
        for (int i = tid; i < NAT * 32; i += 256) {
            int j = i >> 5, sl = i & 31;
            cz[(size_t)j * 65536 + sl] = 0.f;
        }
    }

    // ---- load X tile: sh_x[m][sl] (coalesced) ----
    for (int i = tid; i < 2048; i += 256) {
        int m = i >> 5, sl = i & 31;
        sh_x[i] = zb[m * 1024 + sl];
    }
    __syncthreads();

    // ---- Phase 1: warp-pair GEMM — 8 signals x 8 atoms per thread ----
    {
        const int p2 = wid >> 1;
        const int ph = wid & 1;
        unsigned long long acc[8][4];
        #pragma unroll
        for (int s = 0; s < 8; s++)
            #pragma unroll
            for (int p = 0; p < 4; p++) acc[s][p] = 0ull;

        for (int m = 0; m < MDIM; m++) {
            const ulonglong2* drow = (const ulonglong2*)(&g_dnormJ[m][0]);
            ulonglong2 da = drow[64 * ph + lane];        // quadrant 2ph
            ulonglong2 db = drow[64 * ph + 32 + lane];   // quadrant 2ph+1
            unsigned long long dv[4] = {da.x, da.y, db.x, db.y};
            float4 xa = *(const float4*)(sh_x + m * 32 + p2 * 8);
            float4 xb = *(const float4*)(sh_x + m * 32 + p2 * 8 + 4);
            float xc[8] = {xa.x, xa.y, xa.z, xa.w, xb.x, xb.y, xb.z, xb.w};
            #pragma unroll
            for (int s = 0; s < 8; s++) {
                unsigned long long xp = pack2(xc[s]);
                #pragma unroll
                for (int p = 0; p < 4; p++)
                    acc[s][p] = fma2(dv[p], xp, acc[s][p]);
            }
        }
        // stage to GLOBAL (L2-resident; frees smem -> bigger L1D carveout)
        #pragma unroll
        for (int s = 0; s < 8; s++) {
            const int sl = p2 * 8 + s;
            #pragma unroll
            for (int p = 0; p < 4; p++)
                hb_blk[(((sl & 3) * 8) + ph * 4 + p) * 256 +
                       ((sl >> 2) * 32 + lane)] = acc[s][p];
        }
    }
    __syncthreads();   // orders block-scope global staging (smem AND global)

    // ---- Phase 2: OMP, TWO interleaved chains per warp per pass ----
    #pragma unroll 1
    for (int sp = 0; sp < 2; ++sp) {
        unsigned long long h2[2][8];
        #pragma unroll
        for (int c = 0; c < 2; c++)
            #pragma unroll
            for (int p = 0; p < 8; p++)
                h2[c][p] = hb_blk[((2 * sp + c) * 8 + p) * 256 + tid];

        unsigned mask[2] = {0u, 0u};
        int   idxs[2][5];
        float xs[2][5], y[2][5], rv[2][5], Lm[2][10];
        unsigned labs[2], lj[2], lsgn[2];

        #pragma unroll
        for (int c = 0; c < 2; c++)
            LOCAL_ARGMAX64(h2[c], mask[c], labs[c], lj[c], lsgn[c]);

        #pragma unroll
        for (int k = 0; k < 5; k++) {
            // ---- cross-lane argmax: redux pairs back-to-back (overlap) ----
            unsigned wmax[2], kmin[2];
            #pragma unroll
            for (int c = 0; c < 2; c++)
                wmax[c] = __reduce_max_sync(0xffffffffu, labs[c]);
            #pragma unroll
            for (int c = 0; c < 2; c++) {
                unsigned cand = (labs[c] == wmax[c])
                              ? ((lj[c] << 1) | lsgn[c]) : 0xFFFFFFFFu;
                kmin[c] = __reduce_min_sync(0xffffffffu, cand);
            }

            int bestj[2]; float h_sel[2];
            #pragma unroll
            for (int c = 0; c < 2; c++) {
                bestj[c] = (int)(kmin[c] >> 1);
                float av = __uint_as_float(wmax[c]);
                h_sel[c] = (kmin[c] & 1u) ? -av : av;
                if (((bestj[c] >> 2) & 31) == lane) {
                    int tb = (((bestj[c] >> 7) << 2) | (bestj[c] & 3));
                    mask[c] |= 1u << tb;
                }
                idxs[c][k] = bestj[c];
            }

            // ---- G_stack scalars for Cholesky (critical path: issue first) --
            float gs[2][4];
            #pragma unroll
            for (int c = 0; c < 2; c++)
                #pragma unroll
                for (int i = 0; i < 4; i++) if (i < k)
                    gs[c][i] = __ldg(&g_G[bestj[c]][idxs[c][i]]);

            // ---- register-free prefetch of the NEW Gram row into L1 ----
            // (with the big L1D carveout the row now actually STAYS cached)
            if (k < 4) {
                #pragma unroll
                for (int c = 0; c < 2; c++) {
                    const char* gp = (const char*)(&g_G[bestj[c]][0]) + lane * 16;
                    asm volatile(
                        "prefetch.global.L1 [%0];\n\t"
                        "prefetch.global.L1 [%0+512];\n\t"
                        "prefetch.global.L1 [%0+1024];\n\t"
                        "prefetch.global.L1 [%0+1536];" :: "l"(gp));
                }
            }

            #pragma unroll
            for (int c = 0; c < 2; c++) {
                // ---- incremental Cholesky ----
                if (k == 0) {
                    rv[c][0] = 1.f;
                } else {
                    float w[4]; float s2 = 0.f;
                    #pragma unroll
                    for (int i = 0; i < 4; i++) if (i < k) {
                        float v = gs[c][i];
                        #pragma unroll
                        for (int j2 = 0; j2 < 4; j2++)
                            if (j2 < i) v -= Lm[c][TRI(i, j2)] * w[j2];
                        w[i] = (i == 0) ? v : v * rv[c][i];
                        Lm[c][TRI(k, i)] = w[i];
                        s2 += w[i] * w[i];
                    }
                    rv[c][k] = __frcp_rn(sqrtf(1.f - s2));
                }
                // ---- forward solve collapses exactly:  y_k = h_sel * rinv_k
                y[c][k] = (k == 0) ? h_sel[c] : h_sel[c] * rv[c][k];
            }

            // ---- backward solves with in-place dx (both chains) ----
            float dx[2][5];
            #pragma unroll
            for (int c = 0; c < 2; c++) {
                #pragma unroll
                for (int i = 4; i >= 0; i--) if (i <= k) {
                    float v = y[c][i];
                    #pragma unroll
                    for (int j2 = 0; j2 < 5; j2++)
                        if (j2 > i && j2 <= k) v -= Lm[c][TRI(j2, i)] * xs[c][j2];
                    float xn = (i == 0) ? v : v * rv[c][i];
                    dx[c][i] = (i < k) ? (xn - xs[c][i]) : xn;
                    xs[c][i] = xn;
                }
            }

            // ---- fused: packed delta residual update + NEXT local argmax ----
            if (k < 4) {
                #pragma unroll
                for (int c = 0; c < 2; c++) {
                    #pragma unroll
                    for (int i = 0; i < 4; i++) if (i <= k) {
                        const float4* gri = (const float4*)(&g_G[idxs[c][i]][0]);
                        unsigned long long dxn = pack2(-dx[c][i]);
                        #pragma unroll
                        for (int q = 0; q < 4; q++) {
                            float4 g4 = __ldg(gri + 32 * q + lane);
                            h2[c][2*q]   = fma2(pk2(g4.x, g4.y), dxn, h2[c][2*q]);
                            h2[c][2*q+1] = fma2(pk2(g4.z, g4.w), dxn, h2[c][2*q+1]);
                        }
                    }
                }
                #pragma unroll
                for (int c = 0; c < 2; c++)
                    LOCAL_ARGMAX64(h2[c], mask[c], labs[c], lj[c], lsgn[c]);
            }
        }

        // ---- outputs for both chains ----
        #pragma unroll
        for (int c = 0; c < 2; c++) {
            const int sl = wid * 4 + 2 * sp + c;
            const int s  = tile + sl;
            #pragma unroll
            for (int i = 0; i < 5; i++)
                if (lane == i) out_coef[(size_t)idxs[c][i] * 65536 + s] = xs[c][i];

            float r0 = 0.f, r1 = 0.f;
            #pragma unroll
            for (int i = 0; i < 5; i++) {
                const float* dr = &g_dnormT[idxs[c][i]][0];
                r0 += xs[c][i] * dr[lane];
                r1 += xs[c][i] * dr[lane + 32];
            }
            sh_z[lane * 33 + sl]        = r0;
            sh_z[(lane + 32) * 33 + sl] = r1;
        }
    }
    __syncthreads();

    // ---- Phase 3: coalesced z_dl_st write + loss reduce (fp32 partials) ----
    float partf = 0.f;
    float* oz = out_z + (size_t)b * 65536 + hw0;
    for (int i = tid; i < 2048; i += 256) {
        int m = i >> 5, sl = i & 31;
        float xv = sh_x[m * 32 + sl];
        float r  = sh_z[m * 33 + sl];
        float dd = r - xv;
        partf += dd * dd;
        oz[m * 1024 + sl] = xv + dd;   // z_e + (z_dl - z_e)
    }
    sh_red[tid] = (double)partf;
    __syncthreads();
    for (int sft = 128; sft; sft >>= 1) {
        if (tid < sft) sh_red[tid] += sh_red[tid + sft];
        __syncthreads();
    }

    // ---- fused final loss: last block reduces g_partial deterministically --
    if (tid == 0) {
        g_partial[blockIdx.x] = sh_red[0];
        __threadfence();
        unsigned ticket = atomicAdd(&g_done, 1u);
        sh_last = (ticket == NBLK - 1);
    }
    __syncthreads();
    if (sh_last) {
        double p = 0.0;
        for (int i = tid; i < NBLK; i += 256) p += g_partial[i];
        sh_red[tid] = p;
        __syncthreads();
        for (int sft = 128; sft; sft >>= 1) {
            if (tid < sft) sh_red[tid] += sh_red[tid + sft];
            __syncthreads();
        }
        if (tid == 0) {
            out_loss[0] = (float)(1.25 * sh_red[0] / 4194304.0);
            atomicExch(&g_done, 0u);   // reset for next graph replay
        }
    }
}

// ---------------- launch ------------------------------------------------------
extern "C" void kernel_launch(void* const* d_in, const int* in_sizes, int n_in,
                              void* d_out, int out_size) {
    const float* ze   = (const float*)d_in[0];
    const float* dict = (const float*)d_in[1];
    float* out      = (float*)d_out;
    float* out_z    = out;                 // 4,194,304
    float* out_loss = out + 4194304;       // 1
    float* out_coef = out + 4194305;       // 33,554,432

    cudaFuncSetAttribute(k_main, cudaFuncAttributeMaxDynamicSharedMemorySize,
                         SMEM_BYTES);

    k_prep1<<<NAT, 256>>>(dict);
    k_main<<<NBLK, 256, SMEM_BYTES>>>(ze, out_z, out_coef, out_loss);
}

// round 14
// speedup vs baseline: 1.6000x; 1.6000x over previous
#include <cuda_runtime.h>
#include <math.h>

#define NSIG 65536
#define NAT  512
#define MDIM 64
#define NBLK 2048            // NSIG / 32 signals per block
#define SMEM_FLOATS (2048 + 16384 + 2112)
#define SMEM_BYTES  (SMEM_FLOATS * 4)

// ---------------- device globals (scratch; no allocations allowed) ----------
__device__ __align__(16) float  g_dnormJ[MDIM][NAT];   // [m][j]
__device__ __align__(16) float  g_dnormT[NAT][MDIM];   // [j][m]
__device__ __align__(16) float  g_G[NAT][NAT];         // Gram (scaled)
__device__ double g_partial[NBLK];
__device__ unsigned g_done = 0;

// ---------------- f32x2 packed-FMA helpers (Blackwell) ----------------------
__device__ __forceinline__ unsigned long long fma2(unsigned long long a,
                                                   unsigned long long b,
                                                   unsigned long long c) {
    unsigned long long r;
    asm("fma.rn.f32x2 %0, %1, %2, %3;" : "=l"(r) : "l"(a), "l"(b), "l"(c));
    return r;
}
__device__ __forceinline__ unsigned long long pack2(float x) {
    unsigned long long r;
    asm("mov.b64 %0, {%1, %1};" : "=l"(r) : "f"(x));
    return r;
}
__device__ __forceinline__ unsigned long long pk2(float a, float b) {
    unsigned long long r;
    asm("mov.b64 %0, {%1, %2};" : "=l"(r) : "f"(a), "f"(b));
    return r;
}
__device__ __forceinline__ float2 unpack2(unsigned long long v) {
    float2 f;
    asm("mov.b64 {%0, %1}, %2;" : "=f"(f.x), "=f"(f.y) : "l"(v));
    return f;
}

// ---------------- K-prologue: ONE launch computes everything ----------------
// Block i: redundantly computes all column norms from dict (cheap), writes
// its scaled Gram row G[i][:] and its dnorm column (j = i). No global sync.
__global__ void k_prep1(const float* __restrict__ dict) {
    __shared__ float di[MDIM];
    __shared__ float rni_sh;
    const int i = blockIdx.x, tid = threadIdx.x;
    if (tid < MDIM) di[tid] = __ldg(dict + tid * NAT + i);
    __syncthreads();

    const int j0 = tid, j1 = tid + 256;
    float s0 = 0.f, s1 = 0.f, g0 = 0.f, g1 = 0.f;
    #pragma unroll
    for (int m = 0; m < MDIM; m++) {
        float a  = __ldg(dict + m * NAT + j0);
        float bb = __ldg(dict + m * NAT + j1);
        float dm = di[m];
        s0 += a * a;   s1 += bb * bb;
        g0 += dm * a;  g1 += dm * bb;
    }
    float rn0 = 1.f / fmaxf(sqrtf(s0), 1e-10f);
    float rn1 = 1.f / fmaxf(sqrtf(s1), 1e-10f);
    if (j0 == i) rni_sh = rn0;
    if (j1 == i) rni_sh = rn1;
    __syncthreads();
    const float rni = rni_sh;

    g_G[i][j0] = g0 * rni * rn0;
    g_G[i][j1] = g1 * rni * rn1;

    if (tid < MDIM) {                 // dnorm column i
        float d = di[tid] * rni;
        g_dnormJ[tid][i] = d;
        g_dnormT[i][tid] = d;
    }
}

// atom index owned by (lane, t):  j = 128*(t>>2) + 4*lane + (t&3)
#define JMAP(lane, t) (128 * ((t) >> 2) + 4 * (lane) + ((t) & 3))
#define TRI(i, j) ((i) * ((i) - 1) / 2 + (j))    // lower-tri flat index, i > j

// local masked abs-argmax over 16 owned atoms kept as 8 f32x2 pairs
#define LOCAL_ARGMAX64(h8, mk, LABS, LJ, LSGN) do {                          \
    float v8[8]; int m8[8];                                                  \
    _Pragma("unroll")                                                        \
    for (int p = 0; p < 8; p++) {                                            \
        float2 f = unpack2((h8)[p]);                                         \
        unsigned hb0 = __float_as_uint(f.x);                                 \
        unsigned hb1 = __float_as_uint(f.y);                                 \
        float a0 = (((mk) >> (2*p)) & 1u) ? 0.f                              \
                 : __uint_as_float(hb0 & 0x7FFFFFFFu);                       \
        float a1 = (((mk) >> (2*p+1)) & 1u) ? 0.f                            \
                 : __uint_as_float(hb1 & 0x7FFFFFFFu);                       \
        bool r = a1 > a0;                                                    \
        v8[p] = r ? a1 : a0;                                                 \
        m8[p] = r ? (((2*p+1) << 1) | (int)(hb1 >> 31))                      \
                  : (((2*p)   << 1) | (int)(hb0 >> 31));                     \
    }                                                                        \
    float v4[4]; int m4[4];                                                  \
    _Pragma("unroll")                                                        \
    for (int p = 0; p < 4; p++) {                                            \
        bool r = v8[2*p+1] > v8[2*p];                                        \
        v4[p] = r ? v8[2*p+1] : v8[2*p];                                     \
        m4[p] = r ? m8[2*p+1] : m8[2*p];                                     \
    }                                                                        \
    float v2[2]; int m2[2];                                                  \
    _Pragma("unroll")                                                        \
    for (int p = 0; p < 2; p++) {                                            \
        bool r = v4[2*p+1] > v4[2*p];                                        \
        v2[p] = r ? v4[2*p+1] : v4[2*p];                                     \
        m2[p] = r ? m4[2*p+1] : m4[2*p];                                     \
    }                                                                        \
    bool r1 = v2[1] > v2[0];                                                 \
    float lv = r1 ? v2[1] : v2[0];                                           \
    int   lm = r1 ? m2[1] : m2[0];                                           \
    (LABS) = __float_as_uint(lv);                                            \
    (LJ)   = (unsigned)JMAP(lane, lm >> 1);                                  \
    (LSGN) = (unsigned)(lm & 1);                                             \
} while (0)

// ---------------- K3: fused zero + GEMM + dual-chain OMP + outputs + loss ---
__global__ void __launch_bounds__(256, 2)
k_main(const float* __restrict__ ze, float* __restrict__ out_z,
       float* __restrict__ out_coef, float* __restrict__ out_loss) {
    extern __shared__ float smem[];
    float* sh_x = smem;                                       // [64][32]  2048
    unsigned long long* sh_h64 =
        (unsigned long long*)(smem + 2048);                   // [32][256] u64
    float* sh_z = smem + 2048 + 16384;                        // [64][33]  2112
    __shared__ double sh_red[256];
    __shared__ int sh_last;

    const int tid  = threadIdx.x;
    const int lane = tid & 31;
    const int wid  = tid >> 5;
    const int tile = blockIdx.x * 32;
    const int b    = tile >> 10;
    const int hw0  = tile & 1023;
    const float* zb = ze + (size_t)b * 65536 + hw0;

    // ---- zero this block's 32 coeff columns (hides under GEMM) ----
    {
        float* cz = out_coef + tile;
        for (int i = tid; i < NAT * 32; i += 256) {
            int j = i >> 5, sl = i & 31;
            cz[(size_t)j * 65536 + sl] = 0.f;
        }
    }

    // ---- load X tile: sh_x[m][sl] (coalesced) ----
    for (int i = tid; i < 2048; i += 256) {
        int m = i >> 5, sl = i & 31;
        sh_x[i] = zb[m * 1024 + sl];
    }
    __syncthreads();

    // ---- Phase 1: warp-pair GEMM — 8 signals x 8 atoms per thread ----
    {
        const int p2 = wid >> 1;
        const int ph = wid & 1;
        unsigned long long acc[8][4];
        #pragma unroll
        for (int s = 0; s < 8; s++)
            #pragma unroll
            for (int p = 0; p < 4; p++) acc[s][p] = 0ull;

        for (int m = 0; m < MDIM; m++) {
            const ulonglong2* drow = (const ulonglong2*)(&g_dnormJ[m][0]);
            ulonglong2 da = drow[64 * ph + lane];        // quadrant 2ph
            ulonglong2 db = drow[64 * ph + 32 + lane];   // quadrant 2ph+1
            unsigned long long dv[4] = {da.x, da.y, db.x, db.y};
            float4 xa = *(const float4*)(sh_x + m * 32 + p2 * 8);
            float4 xb = *(const float4*)(sh_x + m * 32 + p2 * 8 + 4);
            float xc[8] = {xa.x, xa.y, xa.z, xa.w, xb.x, xb.y, xb.z, xb.w};
            #pragma unroll
            for (int s = 0; s < 8; s++) {
                unsigned long long xp = pack2(xc[s]);
                #pragma unroll
                for (int p = 0; p < 4; p++)
                    acc[s][p] = fma2(dv[p], xp, acc[s][p]);
            }
        }
        #pragma unroll
        for (int s = 0; s < 8; s++) {
            const int sl = p2 * 8 + s;
            #pragma unroll
            for (int p = 0; p < 4; p++)
                sh_h64[(((sl & 3) * 8) + ph * 4 + p) * 256 +
                       ((sl >> 2) * 32 + lane)] = acc[s][p];
        }
    }
    __syncthreads();   // cross-warp staging

    // ---- Phase 2: OMP, TWO interleaved chains per warp per pass ----
    #pragma unroll 1
    for (int sp = 0; sp < 2; ++sp) {
        unsigned long long h2[2][8];
        #pragma unroll
        for (int c = 0; c < 2; c++)
            #pragma unroll
            for (int p = 0; p < 8; p++)
                h2[c][p] = sh_h64[((2 * sp + c) * 8 + p) * 256 + tid];

        unsigned mask[2] = {0u, 0u};
        int   idxs[2][5];
        float xs[2][5], y[2][5], rv[2][5], Lm[2][10];
        unsigned labs[2], lj[2], lsgn[2];

        #pragma unroll
        for (int c = 0; c < 2; c++)
            LOCAL_ARGMAX64(h2[c], mask[c], labs[c], lj[c], lsgn[c]);

        #pragma unroll
        for (int k = 0; k < 5; k++) {
            // ---- cross-lane argmax: redux pairs back-to-back (overlap) ----
            unsigned wmax[2], kmin[2];
            #pragma unroll
            for (int c = 0; c < 2; c++)
                wmax[c] = __reduce_max_sync(0xffffffffu, labs[c]);
            #pragma unroll
            for (int c = 0; c < 2; c++) {
                unsigned cand = (labs[c] == wmax[c])
                              ? ((lj[c] << 1) | lsgn[c]) : 0xFFFFFFFFu;
                kmin[c] = __reduce_min_sync(0xffffffffu, cand);
            }

            int bestj[2]; float h_sel[2];
            #pragma unroll
            for (int c = 0; c < 2; c++) {
                bestj[c] = (int)(kmin[c] >> 1);
                float av = __uint_as_float(wmax[c]);
                h_sel[c] = (kmin[c] & 1u) ? -av : av;
                if (((bestj[c] >> 2) & 31) == lane) {
                    int tb = (((bestj[c] >> 7) << 2) | (bestj[c] & 3));
                    mask[c] |= 1u << tb;
                }
                idxs[c][k] = bestj[c];
            }

            // ---- G_stack scalars for Cholesky (both chains issued together) --
            float gs[2][4];
            #pragma unroll
            for (int c = 0; c < 2; c++)
                #pragma unroll
                for (int i = 0; i < 4; i++) if (i < k)
                    gs[c][i] = __ldg(&g_G[bestj[c]][idxs[c][i]]);

            #pragma unroll
            for (int c = 0; c < 2; c++) {
                // ---- incremental Cholesky ----
                if (k == 0) {
                    rv[c][0] = 1.f;
                } else {
                    float w[4]; float s2 = 0.f;
                    #pragma unroll
                    for (int i = 0; i < 4; i++) if (i < k) {
                        float v = gs[c][i];
                        #pragma unroll
                        for (int j2 = 0; j2 < 4; j2++)
                            if (j2 < i) v -= Lm[c][TRI(i, j2)] * w[j2];
                        w[i] = (i == 0) ? v : v * rv[c][i];
                        Lm[c][TRI(k, i)] = w[i];
                        s2 += w[i] * w[i];
                    }
                    rv[c][k] = __frcp_rn(sqrtf(1.f - s2));
                }
                // ---- forward solve collapses exactly:  y_k = h_sel * rinv_k
                y[c][k] = (k == 0) ? h_sel[c] : h_sel[c] * rv[c][k];
            }

            // ---- backward solves with in-place dx (both chains) ----
            float dx[2][5];
            #pragma unroll
            for (int c = 0; c < 2; c++) {
                #pragma unroll
                for (int i = 4; i >= 0; i--) if (i <= k) {
                    float v = y[c][i];
                    #pragma unroll
                    for (int j2 = 0; j2 < 5; j2++)
                        if (j2 > i && j2 <= k) v -= Lm[c][TRI(j2, i)] * xs[c][j2];
                    float xn = (i == 0) ? v : v * rv[c][i];
                    dx[c][i] = (i < k) ? (xn - xs[c][i]) : xn;
                    xs[c][i] = xn;
                }
            }

            // ---- fused: packed delta residual update + NEXT local argmax ----
            if (k < 4) {
                #pragma unroll
                for (int c = 0; c < 2; c++) {
                    #pragma unroll
                    for (int i = 0; i < 4; i++) if (i <= k) {
                        const float4* gri = (const float4*)(&g_G[idxs[c][i]][0]);
                        unsigned long long dxn = pack2(-dx[c][i]);
                        #pragma unroll
                        for (int q = 0; q < 4; q++) {
                            float4 g4 = __ldg(gri + 32 * q + lane);
                            h2[c][2*q]   = fma2(pk2(g4.x, g4.y), dxn, h2[c][2*q]);
                            h2[c][2*q+1] = fma2(pk2(g4.z, g4.w), dxn, h2[c][2*q+1]);
                        }
                    }
                }
                #pragma unroll
                for (int c = 0; c < 2; c++)
                    LOCAL_ARGMAX64(h2[c], mask[c], labs[c], lj[c], lsgn[c]);
            }
        }

        // ---- outputs for both chains ----
        #pragma unroll
        for (int c = 0; c < 2; c++) {
            const int sl = wid * 4 + 2 * sp + c;
            const int s  = tile + sl;
            #pragma unroll
            for (int i = 0; i < 5; i++)
                if (lane == i) out_coef[(size_t)idxs[c][i] * 65536 + s] = xs[c][i];

            float r0 = 0.f, r1 = 0.f;
            #pragma unroll
            for (int i = 0; i < 5; i++) {
                const float* dr = &g_dnormT[idxs[c][i]][0];
                r0 += xs[c][i] * dr[lane];
                r1 += xs[c][i] * dr[lane + 32];
            }
            sh_z[lane * 33 + sl]        = r0;
            sh_z[(lane + 32) * 33 + sl] = r1;
        }
    }
    __syncthreads();

    // ---- Phase 3: coalesced z_dl_st write + loss reduce (fp32 partials) ----
    float partf = 0.f;
    float* oz = out_z + (size_t)b * 65536 + hw0;
    for (int i = tid; i < 2048; i += 256) {
        int m = i >> 5, sl = i & 31;
        float xv = sh_x[m * 32 + sl];
        float r  = sh_z[m * 33 + sl];
        float dd = r - xv;
        partf += dd * dd;
        oz[m * 1024 + sl] = xv + dd;   // z_e + (z_dl - z_e)
    }
    sh_red[tid] = (double)partf;
    __syncthreads();
    for (int sft = 128; sft; sft >>= 1) {
        if (tid < sft) sh_red[tid] += sh_red[tid + sft];
        __syncthreads();
    }

    // ---- fused final loss: last block reduces g_partial deterministically --
    if (tid == 0) {
        g_partial[blockIdx.x] = sh_red[0];
        __threadfence();
        unsigned ticket = atomicAdd(&g_done, 1u);
        sh_last = (ticket == NBLK - 1);
    }
    __syncthreads();
    if (sh_last) {
        double p = 0.0;
        for (int i = tid; i < NBLK; i += 256) p += g_partial[i];
        sh_red[tid] = p;
        __syncthreads();
        for (int sft = 128; sft; sft >>= 1) {
            if (tid < sft) sh_red[tid] += sh_red[tid + sft];
            __syncthreads();
        }
        if (tid == 0) {
            out_loss[0] = (float)(1.25 * sh_red[0] / 4194304.0);
            atomicExch(&g_done, 0u);   // reset for next graph replay
        }
    }
}

// ---------------- launch ------------------------------------------------------
extern "C" void kernel_launch(void* const* d_in, const int* in_sizes, int n_in,
                              void* d_out, int out_size) {
    const float* ze   = (const float*)d_in[0];
    const float* dict = (const float*)d_in[1];
    float* out      = (float*)d_out;
    float* out_z    = out;                 // 4,194,304
    float* out_loss = out + 4194304;       // 1
    float* out_coef = out + 4194305;       // 33,554,432

    cudaFuncSetAttribute(k_main, cudaFuncAttributeMaxDynamicSharedMemorySize,
                         SMEM_BYTES);

    k_prep1<<<NAT, 256>>>(dict);
    k_main<<<NBLK, 256, SMEM_BYTES>>>(ze, out_z, out_coef, out_loss);
}

// round 15
// speedup vs baseline: 1.6107x; 1.0067x over previous
#include <cuda_runtime.h>
#include <math.h>

#define NSIG 65536
#define NAT  512
#define MDIM 64
#define NBLK 2048            // NSIG / 32 signals per block
#define SMEM_FLOATS (2048 + 16384 + 2112)
#define SMEM_BYTES  (SMEM_FLOATS * 4)

// ---------------- device globals (scratch; no allocations allowed) ----------
__device__ __align__(16) float  g_dnormJ[MDIM][NAT];   // [m][j]
__device__ __align__(16) float  g_dnormT[NAT][MDIM];   // [j][m]
__device__ __align__(16) float  g_G[NAT][NAT];         // Gram (scaled)
__device__ double g_partial[NBLK];
__device__ unsigned g_done = 0;

// ---------------- f32x2 packed-FMA helpers (Blackwell) ----------------------
__device__ __forceinline__ unsigned long long fma2(unsigned long long a,
                                                   unsigned long long b,
                                                   unsigned long long c) {
    unsigned long long r;
    asm("fma.rn.f32x2 %0, %1, %2, %3;" : "=l"(r) : "l"(a), "l"(b), "l"(c));
    return r;
}
__device__ __forceinline__ unsigned long long pack2(float x) {
    unsigned long long r;
    asm("mov.b64 %0, {%1, %1};" : "=l"(r) : "f"(x));
    return r;
}
__device__ __forceinline__ unsigned long long pk2(float a, float b) {
    unsigned long long r;
    asm("mov.b64 %0, {%1, %2};" : "=l"(r) : "f"(a), "f"(b));
    return r;
}
__device__ __forceinline__ float2 unpack2(unsigned long long v) {
    float2 f;
    asm("mov.b64 {%0, %1}, %2;" : "=f"(f.x), "=f"(f.y) : "l"(v));
    return f;
}

// ---------------- K-prologue: ONE launch computes everything ----------------
__global__ void k_prep1(const float* __restrict__ dict) {
    __shared__ float di[MDIM];
    __shared__ float rni_sh;
    const int i = blockIdx.x, tid = threadIdx.x;
    if (tid < MDIM) di[tid] = __ldg(dict + tid * NAT + i);
    __syncthreads();

    const int j0 = tid, j1 = tid + 256;
    float s0 = 0.f, s1 = 0.f, g0 = 0.f, g1 = 0.f;
    #pragma unroll
    for (int m = 0; m < MDIM; m++) {
        float a  = __ldg(dict + m * NAT + j0);
        float bb = __ldg(dict + m * NAT + j1);
        float dm = di[m];
        s0 += a * a;   s1 += bb * bb;
        g0 += dm * a;  g1 += dm * bb;
    }
    float rn0 = 1.f / fmaxf(sqrtf(s0), 1e-10f);
    float rn1 = 1.f / fmaxf(sqrtf(s1), 1e-10f);
    if (j0 == i) rni_sh = rn0;
    if (j1 == i) rni_sh = rn1;
    __syncthreads();
    const float rni = rni_sh;

    g_G[i][j0] = g0 * rni * rn0;
    g_G[i][j1] = g1 * rni * rn1;

    if (tid < MDIM) {                 // dnorm column i
        float d = di[tid] * rni;
        g_dnormJ[tid][i] = d;
        g_dnormT[i][tid] = d;
    }
}

// atom index owned by (lane, t):  j = 128*(t>>2) + 4*lane + (t&3)
#define JMAP(lane, t) (128 * ((t) >> 2) + 4 * (lane) + ((t) & 3))
#define TRI(i, j) ((i) * ((i) - 1) / 2 + (j))    // lower-tri flat index, i > j

// local masked abs-argmax over 16 owned atoms kept as 8 f32x2 pairs
#define LOCAL_ARGMAX64(h8, mk, LABS, LJ, LSGN) do {                          \
    float v8[8]; int m8[8];                                                  \
    _Pragma("unroll")                                                        \
    for (int p = 0; p < 8; p++) {                                            \
        float2 f = unpack2((h8)[p]);                                         \
        unsigned hb0 = __float_as_uint(f.x);                                 \
        unsigned hb1 = __float_as_uint(f.y);                                 \
        float a0 = (((mk) >> (2*p)) & 1u) ? 0.f                              \
                 : __uint_as_float(hb0 & 0x7FFFFFFFu);                       \
        float a1 = (((mk) >> (2*p+1)) & 1u) ? 0.f                            \
                 : __uint_as_float(hb1 & 0x7FFFFFFFu);                       \
        bool r = a1 > a0;                                                    \
        v8[p] = r ? a1 : a0;                                                 \
        m8[p] = r ? (((2*p+1) << 1) | (int)(hb1 >> 31))                      \
                  : (((2*p)   << 1) | (int)(hb0 >> 31));                     \
    }                                                                        \
    float v4[4]; int m4[4];                                                  \
    _Pragma("unroll")                                                        \
    for (int p = 0; p < 4; p++) {                                            \
        bool r = v8[2*p+1] > v8[2*p];                                        \
        v4[p] = r ? v8[2*p+1] : v8[2*p];                                     \
        m4[p] = r ? m8[2*p+1] : m8[2*p];                                     \
    }                                                                        \
    float v2[2]; int m2[2];                                                  \
    _Pragma("unroll")                                                        \
    for (int p = 0; p < 2; p++) {                                            \
        bool r = v4[2*p+1] > v4[2*p];                                        \
        v2[p] = r ? v4[2*p+1] : v4[2*p];                                     \
        m2[p] = r ? m4[2*p+1] : m4[2*p];                                     \
    }                                                                        \
    bool r1 = v2[1] > v2[0];                                                 \
    float lv = r1 ? v2[1] : v2[0];                                           \
    int   lm = r1 ? m2[1] : m2[0];                                           \
    (LABS) = __float_as_uint(lv);                                            \
    (LJ)   = (unsigned)JMAP(lane, lm >> 1);                                  \
    (LSGN) = (unsigned)(lm & 1);                                             \
} while (0)

// ---------------- K3: fused zero + GEMM + dual-chain OMP + outputs + loss ---
__global__ void __launch_bounds__(256, 2)
k_main(const float* __restrict__ ze, float* __restrict__ out_z,
       float* __restrict__ out_coef, float* __restrict__ out_loss) {
    extern __shared__ float smem[];
    float* sh_x = smem;                                       // [64][32]  2048
    unsigned long long* sh_h64 =
        (unsigned long long*)(smem + 2048);                   // [32][256] u64
    float* sh_z = smem + 2048 + 16384;                        // [64][33]  2112
    __shared__ double sh_red[256];
    __shared__ int sh_last;

    const int tid  = threadIdx.x;
    const int lane = tid & 31;
    const int wid  = tid >> 5;
    const int tile = blockIdx.x * 32;
    const int b    = tile >> 10;
    const int hw0  = tile & 1023;
    const float* zb = ze + (size_t)b * 65536 + hw0;

    // ---- zero this block's 32 coeff columns (hides under GEMM) ----
    {
        float* cz = out_coef + tile;
        for (int i = tid; i < NAT * 32; i += 256) {
            int j = i >> 5, sl = i & 31;
            cz[(size_t)j * 65536 + sl] = 0.f;
        }
    }

    // ---- load X tile: sh_x[m][sl] (coalesced) ----
    for (int i = tid; i < 2048; i += 256) {
        int m = i >> 5, sl = i & 31;
        sh_x[i] = zb[m * 1024 + sl];
    }
    __syncthreads();

    // ---- Phase 1: warp-pair GEMM — 8 signals x 8 atoms per thread ----
    {
        const int p2 = wid >> 1;
        const int ph = wid & 1;
        unsigned long long acc[8][4];
        #pragma unroll
        for (int s = 0; s < 8; s++)
            #pragma unroll
            for (int p = 0; p < 4; p++) acc[s][p] = 0ull;

        for (int m = 0; m < MDIM; m++) {
            const ulonglong2* drow = (const ulonglong2*)(&g_dnormJ[m][0]);
            ulonglong2 da = drow[64 * ph + lane];        // quadrant 2ph
            ulonglong2 db = drow[64 * ph + 32 + lane];   // quadrant 2ph+1
            unsigned long long dv[4] = {da.x, da.y, db.x, db.y};
            float4 xa = *(const float4*)(sh_x + m * 32 + p2 * 8);
            float4 xb = *(const float4*)(sh_x + m * 32 + p2 * 8 + 4);
            float xc[8] = {xa.x, xa.y, xa.z, xa.w, xb.x, xb.y, xb.z, xb.w};
            #pragma unroll
            for (int s = 0; s < 8; s++) {
                unsigned long long xp = pack2(xc[s]);
                #pragma unroll
                for (int p = 0; p < 4; p++)
                    acc[s][p] = fma2(dv[p], xp, acc[s][p]);
            }
        }
        #pragma unroll
        for (int s = 0; s < 8; s++) {
            const int sl = p2 * 8 + s;
            #pragma unroll
            for (int p = 0; p < 4; p++)
                sh_h64[(((sl & 3) * 8) + ph * 4 + p) * 256 +
                       ((sl >> 2) * 32 + lane)] = acc[s][p];
        }
    }
    __syncthreads();   // cross-warp staging

    // ---- Phase 2: OMP, TWO interleaved chains per warp per pass ----
    #pragma unroll 1
    for (int sp = 0; sp < 2; ++sp) {
        unsigned long long h2[2][8];
        #pragma unroll
        for (int c = 0; c < 2; c++)
            #pragma unroll
            for (int p = 0; p < 8; p++)
                h2[c][p] = sh_h64[((2 * sp + c) * 8 + p) * 256 + tid];

        unsigned mask[2] = {0u, 0u};
        int   idxs[2][5];
        float xs[2][5], y[2][5], rv[2][5], Lm[2][10];
        unsigned labs[2], lj[2], lsgn[2];

        #pragma unroll
        for (int c = 0; c < 2; c++)
            LOCAL_ARGMAX64(h2[c], mask[c], labs[c], lj[c], lsgn[c]);

        #pragma unroll
        for (int k = 0; k < 5; k++) {
            // ---- cross-lane argmax: redux pairs back-to-back (overlap) ----
            unsigned wmax[2], kmin[2];
            #pragma unroll
            for (int c = 0; c < 2; c++)
                wmax[c] = __reduce_max_sync(0xffffffffu, labs[c]);
            #pragma unroll
            for (int c = 0; c < 2; c++) {
                unsigned cand = (labs[c] == wmax[c])
                              ? ((lj[c] << 1) | lsgn[c]) : 0xFFFFFFFFu;
                kmin[c] = __reduce_min_sync(0xffffffffu, cand);
            }

            int bestj[2]; float h_sel[2];
            #pragma unroll
            for (int c = 0; c < 2; c++) {
                bestj[c] = (int)(kmin[c] >> 1);
                float av = __uint_as_float(wmax[c]);
                h_sel[c] = (kmin[c] & 1u) ? -av : av;
                if (((bestj[c] >> 2) & 31) == lane) {
                    int tb = (((bestj[c] >> 7) << 2) | (bestj[c] & 3));
                    mask[c] |= 1u << tb;
                }
                idxs[c][k] = bestj[c];
            }

            // ---- G_stack scalars for Cholesky (both chains issued together) --
            float gs[2][4];
            #pragma unroll
            for (int c = 0; c < 2; c++)
                #pragma unroll
                for (int i = 0; i < 4; i++) if (i < k)
                    gs[c][i] = __ldg(&g_G[bestj[c]][idxs[c][i]]);

            #pragma unroll
            for (int c = 0; c < 2; c++) {
                // ---- incremental Cholesky ----
                if (k == 0) {
                    rv[c][0] = 1.f;
                } else {
                    float w[4]; float s2 = 0.f;
                    #pragma unroll
                    for (int i = 0; i < 4; i++) if (i < k) {
                        float v = gs[c][i];
                        #pragma unroll
                        for (int j2 = 0; j2 < 4; j2++)
                            if (j2 < i) v -= Lm[c][TRI(i, j2)] * w[j2];
                        w[i] = (i == 0) ? v : v * rv[c][i];
                        Lm[c][TRI(k, i)] = w[i];
                        s2 += w[i] * w[i];
                    }
                    rv[c][k] = __frcp_rn(sqrtf(1.f - s2));
                }
                // ---- forward solve collapses exactly:  y_k = h_sel * rinv_k
                y[c][k] = (k == 0) ? h_sel[c] : h_sel[c] * rv[c][k];
            }

            if (k < 4) {
                // ---- rank-1 coefficient delta:  dx = y_k * u,  L^T u = e_k --
                // (exact identity: xs_new = [xs_old;0] + y_k * L^{-T} e_k,
                //  since y[0..k-1] are unchanged at step k)
                float dx[2][5];
                #pragma unroll
                for (int c = 0; c < 2; c++) {
                    float u[5];
                    #pragma unroll
                    for (int i = 4; i >= 0; i--) if (i <= k) {
                        if (i == k) {
                            u[i] = rv[c][k];           // rv[0]==1 when k==0
                        } else {
                            float s = 0.f;
                            #pragma unroll
                            for (int j2 = 0; j2 < 5; j2++)
                                if (j2 > i && j2 <= k)
                                    s += Lm[c][TRI(j2, i)] * u[j2];
                            u[i] = (i == 0) ? -s : -rv[c][i] * s;
                        }
                    }
                    #pragma unroll
                    for (int i = 0; i < 5; i++) if (i <= k)
                        dx[c][i] = y[c][k] * u[i];
                }

                // ---- fused: packed delta residual update + NEXT local argmax
                #pragma unroll
                for (int c = 0; c < 2; c++) {
                    #pragma unroll
                    for (int i = 0; i < 4; i++) if (i <= k) {
                        const float4* gri = (const float4*)(&g_G[idxs[c][i]][0]);
                        unsigned long long dxn = pack2(-dx[c][i]);
                        #pragma unroll
                        for (int q = 0; q < 4; q++) {
                            float4 g4 = __ldg(gri + 32 * q + lane);
                            h2[c][2*q]   = fma2(pk2(g4.x, g4.y), dxn, h2[c][2*q]);
                            h2[c][2*q+1] = fma2(pk2(g4.z, g4.w), dxn, h2[c][2*q+1]);
                        }
                    }
                }
                #pragma unroll
                for (int c = 0; c < 2; c++)
                    LOCAL_ARGMAX64(h2[c], mask[c], labs[c], lj[c], lsgn[c]);
            } else {
                // ---- k == 4: single final backward solve for xs (output) ---
                #pragma unroll
                for (int c = 0; c < 2; c++) {
                    #pragma unroll
                    for (int i = 4; i >= 0; i--) {
                        float v = y[c][i];
                        #pragma unroll
                        for (int j2 = 0; j2 < 5; j2++)
                            if (j2 > i) v -= Lm[c][TRI(j2, i)] * xs[c][j2];
                        xs[c][i] = (i == 0) ? v : v * rv[c][i];
                    }
                }
            }
        }

        // ---- outputs for both chains ----
        #pragma unroll
        for (int c = 0; c < 2; c++) {
            const int sl = wid * 4 + 2 * sp + c;
            const int s  = tile + sl;
            #pragma unroll
            for (int i = 0; i < 5; i++)
                if (lane == i) out_coef[(size_t)idxs[c][i] * 65536 + s] = xs[c][i];

            float r0 = 0.f, r1 = 0.f;
            #pragma unroll
            for (int i = 0; i < 5; i++) {
                const float* dr = &g_dnormT[idxs[c][i]][0];
                r0 += xs[c][i] * dr[lane];
                r1 += xs[c][i] * dr[lane + 32];
            }
            sh_z[lane * 33 + sl]        = r0;
            sh_z[(lane + 32) * 33 + sl] = r1;
        }
    }
    __syncthreads();

    // ---- Phase 3: coalesced z_dl_st write + loss reduce (fp32 partials) ----
    float partf = 0.f;
    float* oz = out_z + (size_t)b * 65536 + hw0;
    for (int i = tid; i < 2048; i += 256) {
        int m = i >> 5, sl = i & 31;
        float xv = sh_x[m * 32 + sl];
        float r  = sh_z[m * 33 + sl];
        float dd = r - xv;
        partf += dd * dd;
        oz[m * 1024 + sl] = xv + dd;   // z_e + (z_dl - z_e)
    }
    sh_red[tid] = (double)partf;
    __syncthreads();
    for (int sft = 128; sft; sft >>= 1) {
        if (tid < sft) sh_red[tid] += sh_red[tid + sft];
        __syncthreads();
    }

    // ---- fused final loss: last block reduces g_partial deterministically --
    if (tid == 0) {
        g_partial[blockIdx.x] = sh_red[0];
        __threadfence();
        unsigned ticket = atomicAdd(&g_done, 1u);
        sh_last = (ticket == NBLK - 1);
    }
    __syncthreads();
    if (sh_last) {
        double p = 0.0;
        for (int i = tid; i < NBLK; i += 256) p += g_partial[i];
        sh_red[tid] = p;
        __syncthreads();
        for (int sft = 128; sft; sft >>= 1) {
            if (tid < sft) sh_red[tid] += sh_red[tid + sft];
            __syncthreads();
        }
        if (tid == 0) {
            out_loss[0] = (float)(1.25 * sh_red[0] / 4194304.0);
            atomicExch(&g_done, 0u);   // reset for next graph replay
        }
    }
}

// ---------------- launch ------------------------------------------------------
extern "C" void kernel_launch(void* const* d_in, const int* in_sizes, int n_in,
                              void* d_out, int out_size) {
    const float* ze   = (const float*)d_in[0];
    const float* dict = (const float*)d_in[1];
    float* out      = (float*)d_out;
    float* out_z    = out;                 // 4,194,304
    float* out_loss = out + 4194304;       // 1
    float* out_coef = out + 4194305;       // 33,554,432

    cudaFuncSetAttribute(k_main, cudaFuncAttributeMaxDynamicSharedMemorySize,
                         SMEM_BYTES);

    k_prep1<<<NAT, 256>>>(dict);
    k_main<<<NBLK, 256, SMEM_BYTES>>>(ze, out_z, out_coef, out_loss);
}

// round 16
// speedup vs baseline: 1.6684x; 1.0358x over previous
#include <cuda_runtime.h>
#include <math.h>

#define NSIG 65536
#define NAT  512
#define MDIM 64
#define NBLK 2048            // NSIG / 32 signals per block
#define SMEM_FLOATS (2048 + 16384 + 2112)
#define SMEM_BYTES  (SMEM_FLOATS * 4)

// ---------------- device globals (scratch; no allocations allowed) ----------
__device__ __align__(16) float  g_dnormJ[MDIM][NAT];   // [m][j]
__device__ __align__(16) float  g_dnormT[NAT][MDIM];   // [j][m]
__device__ __align__(16) float  g_G[NAT][NAT];         // Gram (scaled)
__device__ double g_partial[NBLK];
__device__ unsigned g_done = 0;

// ---------------- f32x2 packed-FMA helpers (Blackwell) ----------------------
__device__ __forceinline__ unsigned long long fma2(unsigned long long a,
                                                   unsigned long long b,
                                                   unsigned long long c) {
    unsigned long long r;
    asm("fma.rn.f32x2 %0, %1, %2, %3;" : "=l"(r) : "l"(a), "l"(b), "l"(c));
    return r;
}
__device__ __forceinline__ unsigned long long pack2(float x) {
    unsigned long long r;
    asm("mov.b64 %0, {%1, %1};" : "=l"(r) : "f"(x));
    return r;
}
__device__ __forceinline__ unsigned long long pk2(float a, float b) {
    unsigned long long r;
    asm("mov.b64 %0, {%1, %2};" : "=l"(r) : "f"(a), "f"(b));
    return r;
}
__device__ __forceinline__ float2 unpack2(unsigned long long v) {
    float2 f;
    asm("mov.b64 {%0, %1}, %2;" : "=f"(f.x), "=f"(f.y) : "l"(v));
    return f;
}

// ---------------- K-prologue: ONE launch computes everything ----------------
__global__ void k_prep1(const float* __restrict__ dict) {
    __shared__ float di[MDIM];
    __shared__ float rni_sh;
    const int i = blockIdx.x, tid = threadIdx.x;
    if (tid < MDIM) di[tid] = __ldg(dict + tid * NAT + i);
    __syncthreads();

    const int j0 = tid, j1 = tid + 256;
    float s0 = 0.f, s1 = 0.f, g0 = 0.f, g1 = 0.f;
    #pragma unroll
    for (int m = 0; m < MDIM; m++) {
        float a  = __ldg(dict + m * NAT + j0);
        float bb = __ldg(dict + m * NAT + j1);
        float dm = di[m];
        s0 += a * a;   s1 += bb * bb;
        g0 += dm * a;  g1 += dm * bb;
    }
    float rn0 = 1.f / fmaxf(sqrtf(s0), 1e-10f);
    float rn1 = 1.f / fmaxf(sqrtf(s1), 1e-10f);
    if (j0 == i) rni_sh = rn0;
    if (j1 == i) rni_sh = rn1;
    __syncthreads();
    const float rni = rni_sh;

    g_G[i][j0] = g0 * rni * rn0;
    g_G[i][j1] = g1 * rni * rn1;

    if (tid < MDIM) {                 // dnorm column i
        float d = di[tid] * rni;
        g_dnormJ[tid][i] = d;
        g_dnormT[i][tid] = d;
    }
}

// atom index owned by (lane, t):  j = 128*(t>>2) + 4*lane + (t&3)
#define JMAP(lane, t) (128 * ((t) >> 2) + 4 * (lane) + ((t) & 3))
#define TRI(i, j) ((i) * ((i) - 1) / 2 + (j))    // lower-tri flat index, i > j

// local masked abs-argmax over 16 owned atoms kept as 8 f32x2 pairs
#define LOCAL_ARGMAX64(h8, mk, LABS, LJ, LSGN) do {                          \
    float v8[8]; int m8[8];                                                  \
    _Pragma("unroll")                                                        \
    for (int p = 0; p < 8; p++) {                                            \
        float2 f = unpack2((h8)[p]);                                         \
        unsigned hb0 = __float_as_uint(f.x);                                 \
        unsigned hb1 = __float_as_uint(f.y);                                 \
        float a0 = (((mk) >> (2*p)) & 1u) ? 0.f                              \
                 : __uint_as_float(hb0 & 0x7FFFFFFFu);                       \
        float a1 = (((mk) >> (2*p+1)) & 1u) ? 0.f                            \
                 : __uint_as_float(hb1 & 0x7FFFFFFFu);                       \
        bool r = a1 > a0;                                                    \
        v8[p] = r ? a1 : a0;                                                 \
        m8[p] = r ? (((2*p+1) << 1) | (int)(hb1 >> 31))                      \
                  : (((2*p)   << 1) | (int)(hb0 >> 31));                     \
    }                                                                        \
    float v4[4]; int m4[4];                                                  \
    _Pragma("unroll")                                                        \
    for (int p = 0; p < 4; p++) {                                            \
        bool r = v8[2*p+1] > v8[2*p];                                        \
        v4[p] = r ? v8[2*p+1] : v8[2*p];                                     \
        m4[p] = r ? m8[2*p+1] : m8[2*p];                                     \
    }                                                                        \
    float v2[2]; int m2[2];                                                  \
    _Pragma("unroll")                                                        \
    for (int p = 0; p < 2; p++) {                                            \
        bool r = v4[2*p+1] > v4[2*p];                                        \
        v2[p] = r ? v4[2*p+1] : v4[2*p];                                     \
        m2[p] = r ? m4[2*p+1] : m4[2*p];                                     \
    }                                                                        \
    bool r1 = v2[1] > v2[0];                                                 \
    float lv = r1 ? v2[1] : v2[0];                                           \
    int   lm = r1 ? m2[1] : m2[0];                                           \
    (LABS) = __float_as_uint(lv);                                            \
    (LJ)   = (unsigned)JMAP(lane, lm >> 1);                                  \
    (LSGN) = (unsigned)(lm & 1);                                             \
} while (0)

// ---------------- K3: fused zero + GEMM + dual-chain OMP + outputs + loss ---
__global__ void __launch_bounds__(256, 2)
k_main(const float* __restrict__ ze, float* __restrict__ out_z,
       float* __restrict__ out_coef, float* __restrict__ out_loss) {
    extern __shared__ float smem[];
    float* sh_x = smem;                                       // [64][32]  2048
    unsigned long long* sh_h64 =
        (unsigned long long*)(smem + 2048);                   // [32][256] u64
    float* sh_z = smem + 2048 + 16384;                        // [64][33]  2112
    __shared__ double sh_red[8];
    __shared__ int sh_last;

    const int tid  = threadIdx.x;
    const int lane = tid & 31;
    const int wid  = tid >> 5;
    const int tile = blockIdx.x * 32;
    const int b    = tile >> 10;
    const int hw0  = tile & 1023;
    const float* zb = ze + (size_t)b * 65536 + hw0;

    // ---- zero this block's 32 coeff columns (hides under GEMM) ----
    {
        float* cz = out_coef + tile;
        for (int i = tid; i < NAT * 32; i += 256) {
            int j = i >> 5, sl = i & 31;
            cz[(size_t)j * 65536 + sl] = 0.f;
        }
    }

    // ---- load X tile: sh_x[m][sl] (coalesced) ----
    for (int i = tid; i < 2048; i += 256) {
        int m = i >> 5, sl = i & 31;
        sh_x[i] = zb[m * 1024 + sl];
    }
    __syncthreads();

    // ---- Phase 1: warp-pair GEMM — 8 signals x 8 atoms per thread ----
    {
        const int p2 = wid >> 1;
        const int ph = wid & 1;
        unsigned long long acc[8][4];
        #pragma unroll
        for (int s = 0; s < 8; s++)
            #pragma unroll
            for (int p = 0; p < 4; p++) acc[s][p] = 0ull;

        for (int m = 0; m < MDIM; m++) {
            const ulonglong2* drow = (const ulonglong2*)(&g_dnormJ[m][0]);
            ulonglong2 da = drow[64 * ph + lane];        // quadrant 2ph
            ulonglong2 db = drow[64 * ph + 32 + lane];   // quadrant 2ph+1
            unsigned long long dv[4] = {da.x, da.y, db.x, db.y};
            float4 xa = *(const float4*)(sh_x + m * 32 + p2 * 8);
            float4 xb = *(const float4*)(sh_x + m * 32 + p2 * 8 + 4);
            float xc[8] = {xa.x, xa.y, xa.z, xa.w, xb.x, xb.y, xb.z, xb.w};
            #pragma unroll
            for (int s = 0; s < 8; s++) {
                unsigned long long xp = pack2(xc[s]);
                #pragma unroll
                for (int p = 0; p < 4; p++)
                    acc[s][p] = fma2(dv[p], xp, acc[s][p]);
            }
        }
        #pragma unroll
        for (int s = 0; s < 8; s++) {
            const int sl = p2 * 8 + s;
            #pragma unroll
            for (int p = 0; p < 4; p++)
                sh_h64[(((sl & 3) * 8) + ph * 4 + p) * 256 +
                       ((sl >> 2) * 32 + lane)] = acc[s][p];
        }
    }
    __syncthreads();   // cross-warp staging

    // ---- Phase 2: OMP, TWO interleaved chains per warp per pass ----
    #pragma unroll 1
    for (int sp = 0; sp < 2; ++sp) {
        unsigned long long h2[2][8];
        #pragma unroll
        for (int c = 0; c < 2; c++)
            #pragma unroll
            for (int p = 0; p < 8; p++)
                h2[c][p] = sh_h64[((2 * sp + c) * 8 + p) * 256 + tid];

        unsigned mask[2] = {0u, 0u};
        int   idxs[2][5];
        float xs[2][5], y[2][5], rv[2][5], Lm[2][10];
        unsigned labs[2], lj[2], lsgn[2];

        #pragma unroll
        for (int c = 0; c < 2; c++)
            LOCAL_ARGMAX64(h2[c], mask[c], labs[c], lj[c], lsgn[c]);

        #pragma unroll
        for (int k = 0; k < 5; k++) {
            // ---- cross-lane argmax: redux pairs back-to-back (overlap) ----
            unsigned wmax[2], kmin[2];
            #pragma unroll
            for (int c = 0; c < 2; c++)
                wmax[c] = __reduce_max_sync(0xffffffffu, labs[c]);
            #pragma unroll
            for (int c = 0; c < 2; c++) {
                unsigned cand = (labs[c] == wmax[c])
                              ? ((lj[c] << 1) | lsgn[c]) : 0xFFFFFFFFu;
                kmin[c] = __reduce_min_sync(0xffffffffu, cand);
            }

            int bestj[2]; float h_sel[2];
            #pragma unroll
            for (int c = 0; c < 2; c++) {
                bestj[c] = (int)(kmin[c] >> 1);
                float av = __uint_as_float(wmax[c]);
                h_sel[c] = (kmin[c] & 1u) ? -av : av;
                if (((bestj[c] >> 2) & 31) == lane) {
                    int tb = (((bestj[c] >> 7) << 2) | (bestj[c] & 3));
                    mask[c] |= 1u << tb;
                }
                idxs[c][k] = bestj[c];
            }

            // ---- G_stack scalars for Cholesky (both chains issued together) --
            float gs[2][4];
            #pragma unroll
            for (int c = 0; c < 2; c++)
                #pragma unroll
                for (int i = 0; i < 4; i++) if (i < k)
                    gs[c][i] = __ldg(&g_G[bestj[c]][idxs[c][i]]);

            #pragma unroll
            for (int c = 0; c < 2; c++) {
                // ---- incremental Cholesky ----
                if (k == 0) {
                    rv[c][0] = 1.f;
                } else {
                    float w[4]; float s2 = 0.f;
                    #pragma unroll
                    for (int i = 0; i < 4; i++) if (i < k) {
                        float v = gs[c][i];
                        #pragma unroll
                        for (int j2 = 0; j2 < 4; j2++)
                            if (j2 < i) v -= Lm[c][TRI(i, j2)] * w[j2];
                        w[i] = (i == 0) ? v : v * rv[c][i];
                        Lm[c][TRI(k, i)] = w[i];
                        s2 += w[i] * w[i];
                    }
                    rv[c][k] = __frcp_rn(sqrtf(1.f - s2));
                }
                // ---- forward solve collapses exactly:  y_k = h_sel * rinv_k
                y[c][k] = (k == 0) ? h_sel[c] : h_sel[c] * rv[c][k];
            }

            if (k < 4) {
                // ---- rank-1 coefficient delta:  dx = y_k * u,  L^T u = e_k --
                float dx[2][5];
                #pragma unroll
                for (int c = 0; c < 2; c++) {
                    float u[5];
                    #pragma unroll
                    for (int i = 4; i >= 0; i--) if (i <= k) {
                        if (i == k) {
                            u[i] = rv[c][k];           // rv[0]==1 when k==0
                        } else {
                            float s = 0.f;
                            #pragma unroll
                            for (int j2 = 0; j2 < 5; j2++)
                                if (j2 > i && j2 <= k)
                                    s += Lm[c][TRI(j2, i)] * u[j2];
                            u[i] = (i == 0) ? -s : -rv[c][i] * s;
                        }
                    }
                    #pragma unroll
                    for (int i = 0; i < 5; i++) if (i <= k)
                        dx[c][i] = y[c][k] * u[i];
                }

                // ---- fused residual update, q-OUTER: all (k+1)x2 row-segment
                // loads of one q-block issue together (one L2 latency per q),
                // next q's loads pipeline under this q's FMAs. Accumulation
                // order over i unchanged -> bit-identical h.
                unsigned long long dxn[2][4];
                #pragma unroll
                for (int c = 0; c < 2; c++)
                    #pragma unroll
                    for (int i = 0; i < 4; i++) if (i <= k)
                        dxn[c][i] = pack2(-dx[c][i]);
                #pragma unroll
                for (int q = 0; q < 4; q++) {
                    float4 g4[2][4];
                    #pragma unroll
                    for (int c = 0; c < 2; c++)
                        #pragma unroll
                        for (int i = 0; i < 4; i++) if (i <= k)
                            g4[c][i] = __ldg((const float4*)(&g_G[idxs[c][i]][0])
                                             + 32 * q + lane);
                    #pragma unroll
                    for (int c = 0; c < 2; c++)
                        #pragma unroll
                        for (int i = 0; i < 4; i++) if (i <= k) {
                            h2[c][2*q]   = fma2(pk2(g4[c][i].x, g4[c][i].y),
                                                dxn[c][i], h2[c][2*q]);
                            h2[c][2*q+1] = fma2(pk2(g4[c][i].z, g4[c][i].w),
                                                dxn[c][i], h2[c][2*q+1]);
                        }
                }
                #pragma unroll
                for (int c = 0; c < 2; c++)
                    LOCAL_ARGMAX64(h2[c], mask[c], labs[c], lj[c], lsgn[c]);
            } else {
                // ---- k == 4: single final backward solve for xs (output) ---
                #pragma unroll
                for (int c = 0; c < 2; c++) {
                    #pragma unroll
                    for (int i = 4; i >= 0; i--) {
                        float v = y[c][i];
                        #pragma unroll
                        for (int j2 = 0; j2 < 5; j2++)
                            if (j2 > i) v -= Lm[c][TRI(j2, i)] * xs[c][j2];
                        xs[c][i] = (i == 0) ? v : v * rv[c][i];
                    }
                }
            }
        }

        // ---- outputs for both chains ----
        #pragma unroll
        for (int c = 0; c < 2; c++) {
            const int sl = wid * 4 + 2 * sp + c;
            const int s  = tile + sl;
            #pragma unroll
            for (int i = 0; i < 5; i++)
                if (lane == i) out_coef[(size_t)idxs[c][i] * 65536 + s] = xs[c][i];

            float r0 = 0.f, r1 = 0.f;
            #pragma unroll
            for (int i = 0; i < 5; i++) {
                const float* dr = &g_dnormT[idxs[c][i]][0];
                r0 += xs[c][i] * dr[lane];
                r1 += xs[c][i] * dr[lane + 32];
            }
            sh_z[lane * 33 + sl]        = r0;
            sh_z[(lane + 32) * 33 + sl] = r1;
        }
    }
    __syncthreads();

    // ---- Phase 3: coalesced z_dl_st write + loss reduce (warp shuffles) ----
    float partf = 0.f;
    float* oz = out_z + (size_t)b * 65536 + hw0;
    for (int i = tid; i < 2048; i += 256) {
        int m = i >> 5, sl = i & 31;
        float xv = sh_x[m * 32 + sl];
        float r  = sh_z[m * 33 + sl];
        float dd = r - xv;
        partf += dd * dd;
        oz[m * 1024 + sl] = xv + dd;   // z_e + (z_dl - z_e)
    }
    #pragma unroll
    for (int off = 16; off; off >>= 1)
        partf += __shfl_xor_sync(0xffffffffu, partf, off);
    if (lane == 0) sh_red[wid] = (double)partf;
    __syncthreads();

    // ---- fused final loss: last block reduces g_partial deterministically --
    if (tid == 0) {
        double bp = 0.0;
        #pragma unroll
        for (int wv = 0; wv < 8; wv++) bp += sh_red[wv];
        g_partial[blockIdx.x] = bp;
        __threadfence();
        unsigned ticket = atomicAdd(&g_done, 1u);
        sh_last = (ticket == NBLK - 1);
    }
    __syncthreads();
    if (sh_last) {
        double p = 0.0;
        for (int i = tid; i < NBLK; i += 256) p += g_partial[i];
        // deterministic tree over 256 threads via smem in 8 warp chunks
        #pragma unroll
        for (int off = 16; off; off >>= 1) {
            double o = __longlong_as_double(
                __shfl_xor_sync(0xffffffffu,
                                __double_as_longlong(p), off));
            p += o;
        }
        if (lane == 0) sh_red[wid] = p;
        __syncthreads();
        if (tid == 0) {
            double tot = 0.0;
            #pragma unroll
            for (int wv = 0; wv < 8; wv++) tot += sh_red[wv];
            out_loss[0] = (float)(1.25 * tot / 4194304.0);
            atomicExch(&g_done, 0u);   // reset for next graph replay
        }
    }
}

// ---------------- launch ------------------------------------------------------
extern "C" void kernel_launch(void* const* d_in, const int* in_sizes, int n_in,
                              void* d_out, int out_size) {
    const float* ze   = (const float*)d_in[0];
    const float* dict = (const float*)d_in[1];
    float* out      = (float*)d_out;
    float* out_z    = out;                 // 4,194,304
    float* out_loss = out + 4194304;       // 1
    float* out_coef = out + 4194305;       // 33,554,432

    cudaFuncSetAttribute(k_main, cudaFuncAttributeMaxDynamicSharedMemorySize,
                         SMEM_BYTES);

    k_prep1<<<NAT, 256>>>(dict);
    k_main<<<NBLK, 256, SMEM_BYTES>>>(ze, out_z, out_coef, out_loss);
}